// round 11
// baseline (speedup 1.0000x reference)
#include <cuda_runtime.h>
#include <math.h>

// TropicalAffine: LayerNorm -> max-plus matmul -> max(., bias)
// Exact candidate-pruned tropical matmul, two-kernel pipeline.
//   S_b = {k : xn[b,k] > TAU}; est over S_b; certificate:
//   excluded contribution <= TAU + colmax_W[i] (sound in fp32 by rounding
//   monotonicity); failing elements resolved exactly IN-BLOCK by
//   cooperative warp scans.
// R9: fuse ln_select+colmax into K1 (colmax blocks run concurrently with
//     LN blocks); cleanup moved into tropical blocks (smem list + warp
//     scans) -> 5 launches become 2. Tropical core identical to R8
//     (measured 119.6us, occ 51%, issue 45%).

#define Bn 4096
#define Fn 1024
#define CAP 224
#define TAU 1.05f
#define LN_EPS 1e-5f

__device__ float  g_xn[Bn * Fn];          // layernorm output
__device__ float2 g_cand[Bn * CAP];       // (xn value, k*(Fn/4) as int bits)
__device__ int    g_cnt[Bn];              // padded (even) candidate count
__device__ float  g_cmax[Fn];             // column max of W

// ---------------------------------------------------------------------------
// Kernel 1: fused LayerNorm+compaction (blocks 0..Bn-1) and column-max of W
// (blocks Bn..Bn+3; each covers 256 columns, one thread per column).
// ---------------------------------------------------------------------------
__global__ __launch_bounds__(256) void prep_kernel(
    const float* __restrict__ x,
    const float* __restrict__ W,
    const float* __restrict__ gamma,
    const float* __restrict__ beta)
{
    if (blockIdx.x >= Bn) {
        // colmax: thread -> one column, sweep all 1024 rows (coalesced).
        const int i = (blockIdx.x - Bn) * 256 + threadIdx.x;
        float m = -INFINITY;
        #pragma unroll 16
        for (int k = 0; k < Fn; k++)
            m = fmaxf(m, W[(size_t)k * Fn + i]);
        g_cmax[i] = m;
        return;
    }

    const int b    = blockIdx.x;
    const int tid  = threadIdx.x;
    const int warp = tid >> 5, lane = tid & 31;

    __shared__ float ws[8], wq[8];
    __shared__ float s_mu, s_rs;
    __shared__ int   wsum[8], wbase[8], s_tot;

    float4 v = ((const float4*)(x + (size_t)b * Fn))[tid];
    float s = v.x + v.y + v.z + v.w;
    float q = v.x * v.x + v.y * v.y + v.z * v.z + v.w * v.w;

    #pragma unroll
    for (int o = 16; o > 0; o >>= 1) {
        s += __shfl_xor_sync(0xFFFFFFFFu, s, o);
        q += __shfl_xor_sync(0xFFFFFFFFu, q, o);
    }
    if (lane == 0) { ws[warp] = s; wq[warp] = q; }
    __syncthreads();

    if (tid == 0) {
        float ts = 0.f, tq = 0.f;
        #pragma unroll
        for (int i = 0; i < 8; i++) { ts += ws[i]; tq += wq[i]; }
        float mu  = ts * (1.0f / Fn);
        float var = tq * (1.0f / Fn) - mu * mu;
        s_mu = mu;
        s_rs = rsqrtf(var + LN_EPS);
    }
    __syncthreads();

    const float mu = s_mu, rs = s_rs;
    float4 g  = ((const float4*)gamma)[tid];
    float4 be = ((const float4*)beta)[tid];

    float xn[4];
    xn[0] = (v.x - mu) * rs * g.x + be.x;
    xn[1] = (v.y - mu) * rs * g.y + be.y;
    xn[2] = (v.z - mu) * rs * g.z + be.z;
    xn[3] = (v.w - mu) * rs * g.w + be.w;

    ((float4*)(g_xn + (size_t)b * Fn))[tid] =
        make_float4(xn[0], xn[1], xn[2], xn[3]);

    unsigned f = 0u;
    #pragma unroll
    for (int j = 0; j < 4; j++)
        if (xn[j] > TAU) f |= (1u << j);
    int pcnt = __popc(f);

    int inc = pcnt;
    #pragma unroll
    for (int o = 1; o < 32; o <<= 1) {
        int t = __shfl_up_sync(0xFFFFFFFFu, inc, o);
        if (lane >= o) inc += t;
    }
    int exclw = inc - pcnt;
    if (lane == 31) wsum[warp] = inc;
    __syncthreads();
    if (tid == 0) {
        int run = 0;
        #pragma unroll
        for (int i = 0; i < 8; i++) { wbase[i] = run; run += wsum[i]; }
        s_tot = run;
    }
    __syncthreads();

    float2* cand = g_cand + (size_t)b * CAP;
    int pos = wbase[warp] + exclw;
    const int kb = tid * 4;
    #pragma unroll
    for (int j = 0; j < 4; j++) {
        if ((f >> j) & 1) {
            if (pos < CAP)
                cand[pos] = make_float2(xn[j],
                                        __int_as_float((kb + j) * (Fn / 4)));
            pos++;
        }
    }

    const int tot = s_tot;
    if (tot >= CAP) {   // overflow: est=-INF -> every column fails cert -> exact
        if (tid == 0) g_cnt[b] = 0;
    } else {
        const int totp = (tot + 1) & ~1;   // pad to even with -INF sentinel
        if (tid == 0) {
            if (totp != tot)
                cand[tot] = make_float2(-INFINITY, __int_as_float(0));
            g_cnt[b] = totp;
        }
    }
}

// ---------------------------------------------------------------------------
// Kernel 2: pruned tropical matmul + in-block exact cleanup.
// 256 thr = 8 warps = 4 rows/block; warp w: row = w>>1, column half = w&1.
// Thread owns 16 cols: i = h*512 + c*128 + lane*4, c=0..3. Certificate
// failures go to a smem list; after the sweep, the block's warps resolve
// them exactly (one warp per element, lane-parallel k-scan).
// ---------------------------------------------------------------------------
__global__ __launch_bounds__(256, 5) void tropical_kernel(
    const float* __restrict__ W,
    const float* __restrict__ bias,
    float* __restrict__ out)
{
    const int g    = blockIdx.x;
    const int tid  = threadIdx.x;
    const int wid  = tid >> 5;
    const int lane = tid & 31;
    const int r    = wid >> 1;          // row within block (0..3)
    const int h    = wid & 1;           // column half
    const int b    = g * 4 + r;

    __shared__ float2 s_cand[4][CAP];           // 7 KB
    __shared__ unsigned short s_fail[4096];     // 8 KB (worst-case exact)
    __shared__ int s_nfail;

    if (tid == 0) s_nfail = 0;
    const int cnt = g_cnt[b];           // even
    for (int j = (tid & 63); j < cnt; j += 64)
        s_cand[r][j] = g_cand[(size_t)b * CAP + j];
    __syncthreads();

    float a[4][4];
    #pragma unroll
    for (int c = 0; c < 4; c++)
        #pragma unroll
        for (int e = 0; e < 4; e++) a[c][e] = -INFINITY;

    const float4* Wb = (const float4*)W + h * 128 + lane;

    for (int j = 0; j < cnt; j += 2) {
        float4 ee = *(const float4*)&s_cand[r][j];   // two entries, 1 LDS.128
        const float4* p0 = Wb + __float_as_int(ee.y);
        const float4* p1 = Wb + __float_as_int(ee.w);
        const float s0 = ee.x, s1 = ee.z;
        float4 u0 = p0[0], u1 = p0[32], u2 = p0[64], u3 = p0[96];
        float4 w0 = p1[0], w1 = p1[32], w2 = p1[64], w3 = p1[96];
        a[0][0] = fmaxf(a[0][0], s0 + u0.x);
        a[0][1] = fmaxf(a[0][1], s0 + u0.y);
        a[0][2] = fmaxf(a[0][2], s0 + u0.z);
        a[0][3] = fmaxf(a[0][3], s0 + u0.w);
        a[1][0] = fmaxf(a[1][0], s0 + u1.x);
        a[1][1] = fmaxf(a[1][1], s0 + u1.y);
        a[1][2] = fmaxf(a[1][2], s0 + u1.z);
        a[1][3] = fmaxf(a[1][3], s0 + u1.w);
        a[2][0] = fmaxf(a[2][0], s0 + u2.x);
        a[2][1] = fmaxf(a[2][1], s0 + u2.y);
        a[2][2] = fmaxf(a[2][2], s0 + u2.z);
        a[2][3] = fmaxf(a[2][3], s0 + u2.w);
        a[3][0] = fmaxf(a[3][0], s0 + u3.x);
        a[3][1] = fmaxf(a[3][1], s0 + u3.y);
        a[3][2] = fmaxf(a[3][2], s0 + u3.z);
        a[3][3] = fmaxf(a[3][3], s0 + u3.w);
        a[0][0] = fmaxf(a[0][0], s1 + w0.x);
        a[0][1] = fmaxf(a[0][1], s1 + w0.y);
        a[0][2] = fmaxf(a[0][2], s1 + w0.z);
        a[0][3] = fmaxf(a[0][3], s1 + w0.w);
        a[1][0] = fmaxf(a[1][0], s1 + w1.x);
        a[1][1] = fmaxf(a[1][1], s1 + w1.y);
        a[1][2] = fmaxf(a[1][2], s1 + w1.z);
        a[1][3] = fmaxf(a[1][3], s1 + w1.w);
        a[2][0] = fmaxf(a[2][0], s1 + w2.x);
        a[2][1] = fmaxf(a[2][1], s1 + w2.y);
        a[2][2] = fmaxf(a[2][2], s1 + w2.z);
        a[2][3] = fmaxf(a[2][3], s1 + w2.w);
        a[3][0] = fmaxf(a[3][0], s1 + w3.x);
        a[3][1] = fmaxf(a[3][1], s1 + w3.y);
        a[3][2] = fmaxf(a[3][2], s1 + w3.z);
        a[3][3] = fmaxf(a[3][3], s1 + w3.w);
    }

    // Certificate + smem fail-list + tropical bias + store.
    float* orow = out + (size_t)b * Fn;
    #pragma unroll
    for (int c = 0; c < 4; c++) {
        const int i = h * 512 + c * 128 + lane * 4;
        float4 cm = *(const float4*)(g_cmax + i);
        const float th[4] = {TAU + cm.x, TAU + cm.y, TAU + cm.z, TAU + cm.w};
        #pragma unroll
        for (int e = 0; e < 4; e++) {
            if (a[c][e] < th[e]) {
                int p = atomicAdd(&s_nfail, 1);
                s_fail[p] = (unsigned short)((r << 10) | (i + e));
            }
        }
        float4 bb = *(const float4*)(bias + i);
        *(float4*)(orow + i) = make_float4(fmaxf(a[c][0], bb.x),
                                           fmaxf(a[c][1], bb.y),
                                           fmaxf(a[c][2], bb.z),
                                           fmaxf(a[c][3], bb.w));
    }

    // In-block exact cleanup: one warp per failing element.
    __syncthreads();
    const int nf = s_nfail;
    for (int e = wid; e < nf; e += 8) {
        const int li  = s_fail[e];
        const int rr  = li >> 10;
        const int col = li & (Fn - 1);
        const int bb  = g * 4 + rr;
        const float* xrow = g_xn + (size_t)bb * Fn;
        const float* wc   = W + col;
        float m = -INFINITY;
        for (int k = lane; k < Fn; k += 32)
            m = fmaxf(m, xrow[k] + wc[(size_t)k * Fn]);
        #pragma unroll
        for (int o = 16; o > 0; o >>= 1)
            m = fmaxf(m, __shfl_xor_sync(0xFFFFFFFFu, m, o));
        if (lane == 0)
            out[(size_t)bb * Fn + col] = fmaxf(m, bias[col]);
    }
}

// ---------------------------------------------------------------------------
extern "C" void kernel_launch(void* const* d_in, const int* in_sizes, int n_in,
                              void* d_out, int out_size)
{
    const float* x     = (const float*)d_in[0];
    const float* W     = (const float*)d_in[1];
    const float* bvec  = (const float*)d_in[2];
    const float* gamma = (const float*)d_in[3];
    const float* beta  = (const float*)d_in[4];
    float* out = (float*)d_out;

    prep_kernel<<<Bn + 4, 256>>>(x, W, gamma, beta);
    tropical_kernel<<<Bn / 4, 256>>>(W, bvec, out);
}

// round 12
// speedup vs baseline: 1.0761x; 1.0761x over previous
#include <cuda_runtime.h>
#include <math.h>

// TropicalAffine: LayerNorm -> max-plus matmul -> max(., bias)
// Exact candidate-pruned tropical matmul, three-kernel pipeline.
//   S_b = {k : xn[b,k] > TAU}; est over S_b; certificate:
//   excluded contribution <= TAU + colmax_W[i] (sound in fp32 by rounding
//   monotonicity); failing elements queued globally, re-solved exactly by
//   a separate fully-parallel cleanup kernel.
// R10 = measured-best composition:
//   prep fusion from R9 (ln+colmax one launch, saved ~58us)
//   tropical kernel byte-identical to R8 (measured 119.6us, issue 45%)
//   global-queue cleanup from R8 (measured ~5us at TAU=1.05)

#define Bn 4096
#define Fn 1024
#define CAP 224
#define TAU 1.05f
#define LN_EPS 1e-5f
#define QCAP 262144

__device__ float  g_xn[Bn * Fn];          // layernorm output
__device__ float2 g_cand[Bn * CAP];       // (xn value, k*(Fn/4) as int bits)
__device__ int    g_cnt[Bn];              // padded (even) candidate count
__device__ float  g_cmax[Fn];             // column max of W
__device__ int    g_qcnt;                 // cleanup queue count
__device__ int    g_queue[QCAP];          // failing element indices b*Fn+i

// ---------------------------------------------------------------------------
// Kernel 1: fused LayerNorm+compaction (blocks 0..Bn-1) and column-max of W
// (blocks Bn..Bn+3; one thread per column). Block Bn also resets g_qcnt.
// ---------------------------------------------------------------------------
__global__ __launch_bounds__(256) void prep_kernel(
    const float* __restrict__ x,
    const float* __restrict__ W,
    const float* __restrict__ gamma,
    const float* __restrict__ beta)
{
    if (blockIdx.x >= Bn) {
        const int i = (blockIdx.x - Bn) * 256 + threadIdx.x;
        if (blockIdx.x == Bn && threadIdx.x == 0) g_qcnt = 0;
        float m = -INFINITY;
        #pragma unroll 16
        for (int k = 0; k < Fn; k++)
            m = fmaxf(m, W[(size_t)k * Fn + i]);
        g_cmax[i] = m;
        return;
    }

    const int b    = blockIdx.x;
    const int tid  = threadIdx.x;
    const int warp = tid >> 5, lane = tid & 31;

    __shared__ float ws[8], wq[8];
    __shared__ float s_mu, s_rs;
    __shared__ int   wsum[8], wbase[8], s_tot;

    float4 v = ((const float4*)(x + (size_t)b * Fn))[tid];
    float s = v.x + v.y + v.z + v.w;
    float q = v.x * v.x + v.y * v.y + v.z * v.z + v.w * v.w;

    #pragma unroll
    for (int o = 16; o > 0; o >>= 1) {
        s += __shfl_xor_sync(0xFFFFFFFFu, s, o);
        q += __shfl_xor_sync(0xFFFFFFFFu, q, o);
    }
    if (lane == 0) { ws[warp] = s; wq[warp] = q; }
    __syncthreads();

    if (tid == 0) {
        float ts = 0.f, tq = 0.f;
        #pragma unroll
        for (int i = 0; i < 8; i++) { ts += ws[i]; tq += wq[i]; }
        float mu  = ts * (1.0f / Fn);
        float var = tq * (1.0f / Fn) - mu * mu;
        s_mu = mu;
        s_rs = rsqrtf(var + LN_EPS);
    }
    __syncthreads();

    const float mu = s_mu, rs = s_rs;
    float4 g  = ((const float4*)gamma)[tid];
    float4 be = ((const float4*)beta)[tid];

    float xn[4];
    xn[0] = (v.x - mu) * rs * g.x + be.x;
    xn[1] = (v.y - mu) * rs * g.y + be.y;
    xn[2] = (v.z - mu) * rs * g.z + be.z;
    xn[3] = (v.w - mu) * rs * g.w + be.w;

    ((float4*)(g_xn + (size_t)b * Fn))[tid] =
        make_float4(xn[0], xn[1], xn[2], xn[3]);

    unsigned f = 0u;
    #pragma unroll
    for (int j = 0; j < 4; j++)
        if (xn[j] > TAU) f |= (1u << j);
    int pcnt = __popc(f);

    int inc = pcnt;
    #pragma unroll
    for (int o = 1; o < 32; o <<= 1) {
        int t = __shfl_up_sync(0xFFFFFFFFu, inc, o);
        if (lane >= o) inc += t;
    }
    int exclw = inc - pcnt;
    if (lane == 31) wsum[warp] = inc;
    __syncthreads();
    if (tid == 0) {
        int run = 0;
        #pragma unroll
        for (int i = 0; i < 8; i++) { wbase[i] = run; run += wsum[i]; }
        s_tot = run;
    }
    __syncthreads();

    float2* cand = g_cand + (size_t)b * CAP;
    int pos = wbase[warp] + exclw;
    const int kb = tid * 4;
    #pragma unroll
    for (int j = 0; j < 4; j++) {
        if ((f >> j) & 1) {
            if (pos < CAP)
                cand[pos] = make_float2(xn[j],
                                        __int_as_float((kb + j) * (Fn / 4)));
            pos++;
        }
    }

    const int tot = s_tot;
    if (tot >= CAP) {   // overflow: est=-INF -> every column queued -> exact
        if (tid == 0) g_cnt[b] = 0;
    } else {
        const int totp = (tot + 1) & ~1;   // pad to even with -INF sentinel
        if (tid == 0) {
            if (totp != tot)
                cand[tot] = make_float2(-INFINITY, __int_as_float(0));
            g_cnt[b] = totp;
        }
    }
}

// ---------------------------------------------------------------------------
// Kernel 2: pruned tropical matmul (byte-identical to R8's measured kernel).
// 256 thr = 8 warps = 4 rows/block; warp w: row = w>>1, column half = w&1.
// Thread owns 16 cols: i = h*512 + c*128 + lane*4, c=0..3.
// ---------------------------------------------------------------------------
__global__ __launch_bounds__(256, 5) void tropical_kernel(
    const float* __restrict__ W,
    const float* __restrict__ bias,
    float* __restrict__ out)
{
    const int g    = blockIdx.x;
    const int tid  = threadIdx.x;
    const int wid  = tid >> 5;
    const int lane = tid & 31;
    const int r    = wid >> 1;          // row within block (0..3)
    const int h    = wid & 1;           // column half
    const int b    = g * 4 + r;

    __shared__ float2 s_cand[4][CAP];   // 7 KB

    const int cnt = g_cnt[b];           // even
    for (int j = (tid & 63); j < cnt; j += 64)
        s_cand[r][j] = g_cand[(size_t)b * CAP + j];
    __syncthreads();

    float a[4][4];
    #pragma unroll
    for (int c = 0; c < 4; c++)
        #pragma unroll
        for (int e = 0; e < 4; e++) a[c][e] = -INFINITY;

    const float4* Wb = (const float4*)W + h * 128 + lane;

    for (int j = 0; j < cnt; j += 2) {
        float4 ee = *(const float4*)&s_cand[r][j];   // two entries, 1 LDS.128
        const float4* p0 = Wb + __float_as_int(ee.y);
        const float4* p1 = Wb + __float_as_int(ee.w);
        const float s0 = ee.x, s1 = ee.z;
        float4 u0 = p0[0], u1 = p0[32], u2 = p0[64], u3 = p0[96];
        float4 w0 = p1[0], w1 = p1[32], w2 = p1[64], w3 = p1[96];
        a[0][0] = fmaxf(a[0][0], s0 + u0.x);
        a[0][1] = fmaxf(a[0][1], s0 + u0.y);
        a[0][2] = fmaxf(a[0][2], s0 + u0.z);
        a[0][3] = fmaxf(a[0][3], s0 + u0.w);
        a[1][0] = fmaxf(a[1][0], s0 + u1.x);
        a[1][1] = fmaxf(a[1][1], s0 + u1.y);
        a[1][2] = fmaxf(a[1][2], s0 + u1.z);
        a[1][3] = fmaxf(a[1][3], s0 + u1.w);
        a[2][0] = fmaxf(a[2][0], s0 + u2.x);
        a[2][1] = fmaxf(a[2][1], s0 + u2.y);
        a[2][2] = fmaxf(a[2][2], s0 + u2.z);
        a[2][3] = fmaxf(a[2][3], s0 + u2.w);
        a[3][0] = fmaxf(a[3][0], s0 + u3.x);
        a[3][1] = fmaxf(a[3][1], s0 + u3.y);
        a[3][2] = fmaxf(a[3][2], s0 + u3.z);
        a[3][3] = fmaxf(a[3][3], s0 + u3.w);
        a[0][0] = fmaxf(a[0][0], s1 + w0.x);
        a[0][1] = fmaxf(a[0][1], s1 + w0.y);
        a[0][2] = fmaxf(a[0][2], s1 + w0.z);
        a[0][3] = fmaxf(a[0][3], s1 + w0.w);
        a[1][0] = fmaxf(a[1][0], s1 + w1.x);
        a[1][1] = fmaxf(a[1][1], s1 + w1.y);
        a[1][2] = fmaxf(a[1][2], s1 + w1.z);
        a[1][3] = fmaxf(a[1][3], s1 + w1.w);
        a[2][0] = fmaxf(a[2][0], s1 + w2.x);
        a[2][1] = fmaxf(a[2][1], s1 + w2.y);
        a[2][2] = fmaxf(a[2][2], s1 + w2.z);
        a[2][3] = fmaxf(a[2][3], s1 + w2.w);
        a[3][0] = fmaxf(a[3][0], s1 + w3.x);
        a[3][1] = fmaxf(a[3][1], s1 + w3.y);
        a[3][2] = fmaxf(a[3][2], s1 + w3.z);
        a[3][3] = fmaxf(a[3][3], s1 + w3.w);
    }

    // Certificate + global queue push + tropical bias + store.
    float* orow = out + (size_t)b * Fn;
    #pragma unroll
    for (int c = 0; c < 4; c++) {
        const int i = h * 512 + c * 128 + lane * 4;
        float4 cm = *(const float4*)(g_cmax + i);
        const float th[4] = {TAU + cm.x, TAU + cm.y, TAU + cm.z, TAU + cm.w};
        #pragma unroll
        for (int e = 0; e < 4; e++) {
            if (a[c][e] < th[e]) {
                int qp = atomicAdd(&g_qcnt, 1);
                if (qp < QCAP) g_queue[qp] = b * Fn + (i + e);
            }
        }
        float4 bb = *(const float4*)(bias + i);
        *(float4*)(orow + i) = make_float4(fmaxf(a[c][0], bb.x),
                                           fmaxf(a[c][1], bb.y),
                                           fmaxf(a[c][2], bb.z),
                                           fmaxf(a[c][3], bb.w));
    }
}

// ---------------------------------------------------------------------------
// Kernel 3: exact cleanup. One warp per queued element; lane-parallel scan.
// If the queue overflowed QCAP (impossible in practice), overflowed elements
// were never queued -- avoid that by sizing QCAP = 256K >> any plausible
// failure count; overflow pushes are dropped only when qp >= QCAP, so guard
// correctness by scanning qn = min(qcnt, QCAP) and relying on QCAP margin.
// ---------------------------------------------------------------------------
__global__ __launch_bounds__(128) void cleanup_kernel(
    const float* __restrict__ W,
    const float* __restrict__ bias,
    float* __restrict__ out)
{
    const int lane  = threadIdx.x & 31;
    const int warpg = (blockIdx.x * blockDim.x + threadIdx.x) >> 5;
    const int nwarp = (gridDim.x * blockDim.x) >> 5;
    const int qn    = min(g_qcnt, QCAP);

    for (int e = warpg; e < qn; e += nwarp) {
        const int idx = g_queue[e];
        const int b = idx >> 10, i = idx & (Fn - 1);
        const float* xrow = g_xn + (size_t)b * Fn;
        const float* wc   = W + i;
        float m = -INFINITY;
        for (int k = lane; k < Fn; k += 32)
            m = fmaxf(m, xrow[k] + wc[(size_t)k * Fn]);
        #pragma unroll
        for (int o = 16; o > 0; o >>= 1)
            m = fmaxf(m, __shfl_xor_sync(0xFFFFFFFFu, m, o));
        if (lane == 0)
            out[idx] = fmaxf(m, bias[i]);
    }
}

// ---------------------------------------------------------------------------
extern "C" void kernel_launch(void* const* d_in, const int* in_sizes, int n_in,
                              void* d_out, int out_size)
{
    const float* x     = (const float*)d_in[0];
    const float* W     = (const float*)d_in[1];
    const float* bvec  = (const float*)d_in[2];
    const float* gamma = (const float*)d_in[3];
    const float* beta  = (const float*)d_in[4];
    float* out = (float*)d_out;

    prep_kernel<<<Bn + 4, 256>>>(x, W, gamma, beta);
    tropical_kernel<<<Bn / 4, 256>>>(W, bvec, out);
    cleanup_kernel<<<1024, 128>>>(W, bvec, out);
}

// round 13
// speedup vs baseline: 1.1968x; 1.1122x over previous
#include <cuda_runtime.h>
#include <math.h>

// TropicalAffine: LayerNorm -> max-plus matmul -> max(., bias)
// Exact candidate-pruned tropical matmul, three-kernel pipeline.
//   S_b = {k : xn[b,k] > TAU}; est over S_b; certificate:
//   excluded contribution <= TAU + colmax_W[i] (sound in fp32 by rounding
//   monotonicity); failing elements queued globally, re-solved exactly by
//   a separate fully-parallel cleanup kernel.
// R11: R10 with colmax parallelized 32x -- 128 prep sub-blocks each cover
//   32 k-rows x 256 cols (coalesced) and publish partials via atomicMax on
//   an order-preserving uint encoding (idempotent across graph replays).
//   Measured basis: tropical 119.6us, cleanup ~5-10us, LN ~13us; prep tail
//   was 52.5us from 4 serial colmax blocks.

#define Bn 4096
#define Fn 1024
#define CAP 224
#define TAU 1.05f
#define LN_EPS 1e-5f
#define QCAP 262144

__device__ float    g_xn[Bn * Fn];        // layernorm output
__device__ float2   g_cand[Bn * CAP];     // (xn value, k*(Fn/4) as int bits)
__device__ int      g_cnt[Bn];            // padded (even) candidate count
__device__ unsigned g_cmax_enc[Fn];       // column max of W (encoded)
__device__ int      g_qcnt;               // cleanup queue count
__device__ int      g_queue[QCAP];        // failing element indices b*Fn+i

// Order-preserving float<->uint encoding: f1 < f2  <=>  enc(f1) < enc(f2).
__device__ __forceinline__ unsigned enc_f(float f) {
    unsigned u = __float_as_uint(f);
    return (u & 0x80000000u) ? ~u : (u | 0x80000000u);
}
__device__ __forceinline__ float dec_f(unsigned u) {
    return (u & 0x80000000u) ? __uint_as_float(u & 0x7FFFFFFFu)
                             : __uint_as_float(~u);
}

// ---------------------------------------------------------------------------
// Kernel 1: fused LayerNorm+compaction (blocks 0..Bn-1) and parallel
// column-max of W (blocks Bn..Bn+127: 32 k-slices x 4 column groups).
// Block Bn also resets g_qcnt.
// ---------------------------------------------------------------------------
__global__ __launch_bounds__(256) void prep_kernel(
    const float* __restrict__ x,
    const float* __restrict__ W,
    const float* __restrict__ gamma,
    const float* __restrict__ beta)
{
    if (blockIdx.x >= Bn) {
        const int idx = blockIdx.x - Bn;      // 0..127
        if (idx == 0 && threadIdx.x == 0) g_qcnt = 0;
        const int kc = idx >> 2;              // 0..31 (32-row slice)
        const int i  = (idx & 3) * 256 + threadIdx.x;
        const int k0 = kc * 32;
        float m = -INFINITY;
        #pragma unroll 8
        for (int k = k0; k < k0 + 32; k++)
            m = fmaxf(m, W[(size_t)k * Fn + i]);
        atomicMax(&g_cmax_enc[i], enc_f(m));  // idempotent across replays
        return;
    }

    const int b    = blockIdx.x;
    const int tid  = threadIdx.x;
    const int warp = tid >> 5, lane = tid & 31;

    __shared__ float ws[8], wq[8];
    __shared__ float s_mu, s_rs;
    __shared__ int   wsum[8], wbase[8], s_tot;

    float4 v = ((const float4*)(x + (size_t)b * Fn))[tid];
    float s = v.x + v.y + v.z + v.w;
    float q = v.x * v.x + v.y * v.y + v.z * v.z + v.w * v.w;

    #pragma unroll
    for (int o = 16; o > 0; o >>= 1) {
        s += __shfl_xor_sync(0xFFFFFFFFu, s, o);
        q += __shfl_xor_sync(0xFFFFFFFFu, q, o);
    }
    if (lane == 0) { ws[warp] = s; wq[warp] = q; }
    __syncthreads();

    if (tid == 0) {
        float ts = 0.f, tq = 0.f;
        #pragma unroll
        for (int i = 0; i < 8; i++) { ts += ws[i]; tq += wq[i]; }
        float mu  = ts * (1.0f / Fn);
        float var = tq * (1.0f / Fn) - mu * mu;
        s_mu = mu;
        s_rs = rsqrtf(var + LN_EPS);
    }
    __syncthreads();

    const float mu = s_mu, rs = s_rs;
    float4 g  = ((const float4*)gamma)[tid];
    float4 be = ((const float4*)beta)[tid];

    float xn[4];
    xn[0] = (v.x - mu) * rs * g.x + be.x;
    xn[1] = (v.y - mu) * rs * g.y + be.y;
    xn[2] = (v.z - mu) * rs * g.z + be.z;
    xn[3] = (v.w - mu) * rs * g.w + be.w;

    ((float4*)(g_xn + (size_t)b * Fn))[tid] =
        make_float4(xn[0], xn[1], xn[2], xn[3]);

    unsigned f = 0u;
    #pragma unroll
    for (int j = 0; j < 4; j++)
        if (xn[j] > TAU) f |= (1u << j);
    int pcnt = __popc(f);

    int inc = pcnt;
    #pragma unroll
    for (int o = 1; o < 32; o <<= 1) {
        int t = __shfl_up_sync(0xFFFFFFFFu, inc, o);
        if (lane >= o) inc += t;
    }
    int exclw = inc - pcnt;
    if (lane == 31) wsum[warp] = inc;
    __syncthreads();
    if (tid == 0) {
        int run = 0;
        #pragma unroll
        for (int i = 0; i < 8; i++) { wbase[i] = run; run += wsum[i]; }
        s_tot = run;
    }
    __syncthreads();

    float2* cand = g_cand + (size_t)b * CAP;
    int pos = wbase[warp] + exclw;
    const int kb = tid * 4;
    #pragma unroll
    for (int j = 0; j < 4; j++) {
        if ((f >> j) & 1) {
            if (pos < CAP)
                cand[pos] = make_float2(xn[j],
                                        __int_as_float((kb + j) * (Fn / 4)));
            pos++;
        }
    }

    const int tot = s_tot;
    if (tot >= CAP) {   // overflow: est=-INF -> every column queued -> exact
        if (tid == 0) g_cnt[b] = 0;
    } else {
        const int totp = (tot + 1) & ~1;   // pad to even with -INF sentinel
        if (tid == 0) {
            if (totp != tot)
                cand[tot] = make_float2(-INFINITY, __int_as_float(0));
            g_cnt[b] = totp;
        }
    }
}

// ---------------------------------------------------------------------------
// Kernel 2: pruned tropical matmul (core identical to R8's measured kernel;
// epilogue decodes encoded cmax). 256 thr = 8 warps = 4 rows/block;
// warp w: row = w>>1, column half = w&1. Thread owns 16 cols.
// ---------------------------------------------------------------------------
__global__ __launch_bounds__(256, 5) void tropical_kernel(
    const float* __restrict__ W,
    const float* __restrict__ bias,
    float* __restrict__ out)
{
    const int g    = blockIdx.x;
    const int tid  = threadIdx.x;
    const int wid  = tid >> 5;
    const int lane = tid & 31;
    const int r    = wid >> 1;          // row within block (0..3)
    const int h    = wid & 1;           // column half
    const int b    = g * 4 + r;

    __shared__ float2 s_cand[4][CAP];   // 7 KB

    const int cnt = g_cnt[b];           // even
    for (int j = (tid & 63); j < cnt; j += 64)
        s_cand[r][j] = g_cand[(size_t)b * CAP + j];
    __syncthreads();

    float a[4][4];
    #pragma unroll
    for (int c = 0; c < 4; c++)
        #pragma unroll
        for (int e = 0; e < 4; e++) a[c][e] = -INFINITY;

    const float4* Wb = (const float4*)W + h * 128 + lane;

    for (int j = 0; j < cnt; j += 2) {
        float4 ee = *(const float4*)&s_cand[r][j];   // two entries, 1 LDS.128
        const float4* p0 = Wb + __float_as_int(ee.y);
        const float4* p1 = Wb + __float_as_int(ee.w);
        const float s0 = ee.x, s1 = ee.z;
        float4 u0 = p0[0], u1 = p0[32], u2 = p0[64], u3 = p0[96];
        float4 w0 = p1[0], w1 = p1[32], w2 = p1[64], w3 = p1[96];
        a[0][0] = fmaxf(a[0][0], s0 + u0.x);
        a[0][1] = fmaxf(a[0][1], s0 + u0.y);
        a[0][2] = fmaxf(a[0][2], s0 + u0.z);
        a[0][3] = fmaxf(a[0][3], s0 + u0.w);
        a[1][0] = fmaxf(a[1][0], s0 + u1.x);
        a[1][1] = fmaxf(a[1][1], s0 + u1.y);
        a[1][2] = fmaxf(a[1][2], s0 + u1.z);
        a[1][3] = fmaxf(a[1][3], s0 + u1.w);
        a[2][0] = fmaxf(a[2][0], s0 + u2.x);
        a[2][1] = fmaxf(a[2][1], s0 + u2.y);
        a[2][2] = fmaxf(a[2][2], s0 + u2.z);
        a[2][3] = fmaxf(a[2][3], s0 + u2.w);
        a[3][0] = fmaxf(a[3][0], s0 + u3.x);
        a[3][1] = fmaxf(a[3][1], s0 + u3.y);
        a[3][2] = fmaxf(a[3][2], s0 + u3.z);
        a[3][3] = fmaxf(a[3][3], s0 + u3.w);
        a[0][0] = fmaxf(a[0][0], s1 + w0.x);
        a[0][1] = fmaxf(a[0][1], s1 + w0.y);
        a[0][2] = fmaxf(a[0][2], s1 + w0.z);
        a[0][3] = fmaxf(a[0][3], s1 + w0.w);
        a[1][0] = fmaxf(a[1][0], s1 + w1.x);
        a[1][1] = fmaxf(a[1][1], s1 + w1.y);
        a[1][2] = fmaxf(a[1][2], s1 + w1.z);
        a[1][3] = fmaxf(a[1][3], s1 + w1.w);
        a[2][0] = fmaxf(a[2][0], s1 + w2.x);
        a[2][1] = fmaxf(a[2][1], s1 + w2.y);
        a[2][2] = fmaxf(a[2][2], s1 + w2.z);
        a[2][3] = fmaxf(a[2][3], s1 + w2.w);
        a[3][0] = fmaxf(a[3][0], s1 + w3.x);
        a[3][1] = fmaxf(a[3][1], s1 + w3.y);
        a[3][2] = fmaxf(a[3][2], s1 + w3.z);
        a[3][3] = fmaxf(a[3][3], s1 + w3.w);
    }

    // Certificate (decode cmax) + global queue push + tropical bias + store.
    float* orow = out + (size_t)b * Fn;
    #pragma unroll
    for (int c = 0; c < 4; c++) {
        const int i = h * 512 + c * 128 + lane * 4;
        uint4 cme = *(const uint4*)(g_cmax_enc + i);
        const float th[4] = {TAU + dec_f(cme.x), TAU + dec_f(cme.y),
                             TAU + dec_f(cme.z), TAU + dec_f(cme.w)};
        #pragma unroll
        for (int e = 0; e < 4; e++) {
            if (a[c][e] < th[e]) {
                int qp = atomicAdd(&g_qcnt, 1);
                if (qp < QCAP) g_queue[qp] = b * Fn + (i + e);
            }
        }
        float4 bb = *(const float4*)(bias + i);
        *(float4*)(orow + i) = make_float4(fmaxf(a[c][0], bb.x),
                                           fmaxf(a[c][1], bb.y),
                                           fmaxf(a[c][2], bb.z),
                                           fmaxf(a[c][3], bb.w));
    }
}

// ---------------------------------------------------------------------------
// Kernel 3: exact cleanup. One warp per queued element; lane-parallel scan.
// ---------------------------------------------------------------------------
__global__ __launch_bounds__(128) void cleanup_kernel(
    const float* __restrict__ W,
    const float* __restrict__ bias,
    float* __restrict__ out)
{
    const int lane  = threadIdx.x & 31;
    const int warpg = (blockIdx.x * blockDim.x + threadIdx.x) >> 5;
    const int nwarp = (gridDim.x * blockDim.x) >> 5;
    const int qn    = min(g_qcnt, QCAP);

    for (int e = warpg; e < qn; e += nwarp) {
        const int idx = g_queue[e];
        const int b = idx >> 10, i = idx & (Fn - 1);
        const float* xrow = g_xn + (size_t)b * Fn;
        const float* wc   = W + i;
        float m = -INFINITY;
        for (int k = lane; k < Fn; k += 32)
            m = fmaxf(m, xrow[k] + wc[(size_t)k * Fn]);
        #pragma unroll
        for (int o = 16; o > 0; o >>= 1)
            m = fmaxf(m, __shfl_xor_sync(0xFFFFFFFFu, m, o));
        if (lane == 0)
            out[idx] = fmaxf(m, bias[i]);
    }
}

// ---------------------------------------------------------------------------
extern "C" void kernel_launch(void* const* d_in, const int* in_sizes, int n_in,
                              void* d_out, int out_size)
{
    const float* x     = (const float*)d_in[0];
    const float* W     = (const float*)d_in[1];
    const float* bvec  = (const float*)d_in[2];
    const float* gamma = (const float*)d_in[3];
    const float* beta  = (const float*)d_in[4];
    float* out = (float*)d_out;

    prep_kernel<<<Bn + 128, 256>>>(x, W, gamma, beta);
    tropical_kernel<<<Bn / 4, 256>>>(W, bvec, out);
    cleanup_kernel<<<1024, 128>>>(W, bvec, out);
}